// round 16
// baseline (speedup 1.0000x reference)
#include <cuda_runtime.h>
#include <cuda_bf16.h>
#include <cstdint>

// Sliding-window attention via mma.sync fp16 (fp32 accumulate).
// B=2, S=8192, D=64, window +/-64.
// R16: CTA = 128 queries, 24 warps: 8 row-groups x 3 band-third warps.
// QK->exp->PV fused per k16 tile (live regs ~78 -> 768 threads fit the
// regfile; MUFU/tensor/LDS interleaved instead of phase convoys).
constexpr int Sc = 8192;
constexpr int Dc = 64;
constexpr int TQ = 128;
constexpr int NKC = 256;
constexpr int THREADS = 768;
constexpr float SCALE2 = 0.18033688f;  // 2^-3 * log2(e); exp done as ex2
constexpr int PITCH = 144;     // 144 mod 128 = 16 -> ldmatrix conflict-free

constexpr int SM_KH = 0;                      // fp16 K, 256 rows
constexpr int SM_VH = NKC * PITCH;            // 36864, fp16 V
constexpr int SM_TOTAL = 2 * NKC * PITCH;     // 73728
constexpr int NCH = NKC * 16;                 // 4096 fill chunks

#define LDSM_X4(r0, r1, r2, r3, addr) \
    asm volatile("ldmatrix.sync.aligned.m8n8.x4.shared.b16 {%0,%1,%2,%3}, [%4];" \
                 : "=r"(r0), "=r"(r1), "=r"(r2), "=r"(r3) : "r"(addr))

#define LDSM_X4_T(r0, r1, r2, r3, addr) \
    asm volatile("ldmatrix.sync.aligned.m8n8.x4.trans.shared.b16 {%0,%1,%2,%3}, [%4];" \
                 : "=r"(r0), "=r"(r1), "=r"(r2), "=r"(r3) : "r"(addr))

#define MMA_F16(c, a, b0, b1) \
    asm volatile("mma.sync.aligned.m16n8k16.row.col.f32.f16.f16.f32 " \
                 "{%0,%1,%2,%3},{%4,%5,%6,%7},{%8,%9},{%0,%1,%2,%3};" \
                 : "+f"((c)[0]), "+f"((c)[1]), "+f"((c)[2]), "+f"((c)[3]) \
                 : "r"((a)[0]), "r"((a)[1]), "r"((a)[2]), "r"((a)[3]), "r"(b0), "r"(b1))

__device__ __forceinline__ uint32_t smem_u32(const void* p) {
    uint32_t a;
    asm("{ .reg .u64 t; cvta.to.shared.u64 t, %1; cvt.u32.u64 %0, t; }" : "=r"(a) : "l"(p));
    return a;
}

__device__ __forceinline__ float ex2(float x) {
    float r;
    asm("ex2.approx.f32 %0, %1;" : "=f"(r) : "f"(x));
    return r;
}

// fp16x2 pack, a in low half.
__device__ __forceinline__ uint32_t pack_h2(float a, float b) {
    uint32_t r;
    asm("cvt.rn.f16x2.f32 %0, %1, %2;" : "=r"(r) : "f"(b), "f"(a));
    return r;
}

__device__ __forceinline__ void conv_store(char* smem, int dst, int row, int c4, float4 f) {
    const int off = row * PITCH + c4 * 8;
    *(uint2*)(smem + dst + off) = make_uint2(pack_h2(f.x, f.y), pack_h2(f.z, f.w));
}

// exp + mask + denom + fp16 pack for one n8 tile.
// MODE 0: interior (no predicates); 1: lower band edge; 2: upper band edge;
// 3: border CTA (full checks).
template<int MODE>
__device__ __forceinline__ void exp_t(int T, int ts, int m0, int qrow, int jc,
                                      const float (&s)[4], uint32_t (&ph2)[2],
                                      float& dA, float& dB, float& dC, float& dD)
{
    const int jr = T * 8 + jc;
    float p0, p1, p2, p3;
    if (MODE == 0) {
        p0 = ex2(s[0]); p1 = ex2(s[1]); p2 = ex2(s[2]); p3 = ex2(s[3]);
    } else {
        bool v0, v1, v2, v3;
        if (MODE == 1) {
            v0 = jr >= qrow;      v1 = jr + 1 >= qrow;
            v2 = jr >= qrow + 8;  v3 = jr + 1 >= qrow + 8;
        } else if (MODE == 2) {
            v0 = jr <= qrow + 128; v1 = jr + 1 <= qrow + 128;
            v2 = jr <= qrow + 136; v3 = jr + 1 <= qrow + 136;
        } else {
            const int g0 = ts - 64 + m0 + jr;
            const bool b0 = (unsigned)g0 < (unsigned)Sc;
            const bool b1 = (unsigned)(g0 + 1) < (unsigned)Sc;
            v0 = (jr >= qrow) && (jr <= qrow + 128) && b0;
            v1 = (jr + 1 >= qrow) && (jr + 1 <= qrow + 128) && b1;
            v2 = (jr >= qrow + 8) && (jr <= qrow + 136) && b0;
            v3 = (jr + 1 >= qrow + 8) && (jr + 1 <= qrow + 136) && b1;
        }
        p0 = v0 ? ex2(s[0]) : 0.f;
        p1 = v1 ? ex2(s[1]) : 0.f;
        p2 = v2 ? ex2(s[2]) : 0.f;
        p3 = v3 ? ex2(s[3]) : 0.f;
    }
    dA += p0; dB += p1; dC += p2; dD += p3;
    ph2[0] = pack_h2(p0, p1);   // rows qrow   (A-frag a0/a2 pair)
    ph2[1] = pack_h2(p2, p3);   // rows qrow+8 (A-frag a1/a3 pair)
}

// One fused k16 tile: QK (4 dt) -> exp both n8 tiles -> PV (4 dp).
template<int MA, int MB>
__device__ __forceinline__ void tile_step(int kt, uint32_t smb, int m0,
                                          int krow, int kcol, int vrow, int vcol,
                                          int ts, int qrow, int jc,
                                          const uint32_t (&qh)[4][4],
                                          float (&oacc)[8][4],
                                          float& dA, float& dB, float& dC, float& dD)
{
    float s0[4] = {0.f, 0.f, 0.f, 0.f};
    float s1[4] = {0.f, 0.f, 0.f, 0.f};
    const int rowbK = (m0 + kt * 16 + krow) * PITCH;
    #pragma unroll
    for (int dt = 0; dt < 4; ++dt) {
        uint32_t k0, k1, k2, k3;
        LDSM_X4(k0, k1, k2, k3, smb + SM_KH + rowbK + (dt * 16 + kcol) * 2);
        MMA_F16(s0, qh[dt], k0, k1);
        MMA_F16(s1, qh[dt], k2, k3);
    }
    uint32_t ph0[2], ph1[2];
    exp_t<MA>(2 * kt,     ts, m0, qrow, jc, s0, ph0, dA, dB, dC, dD);
    exp_t<MB>(2 * kt + 1, ts, m0, qrow, jc, s1, ph1, dA, dB, dC, dD);
    const uint32_t ah[4] = { ph0[0], ph0[1], ph1[0], ph1[1] };
    const int rowbV = (m0 + kt * 16 + vrow) * PITCH;
    #pragma unroll
    for (int dp = 0; dp < 4; ++dp) {
        uint32_t v0, v1, v2, v3;
        LDSM_X4_T(v0, v1, v2, v3, smb + SM_VH + rowbV + (dp * 16 + vcol) * 2);
        MMA_F16(oacc[2 * dp],     ah, v0, v1);
        MMA_F16(oacc[2 * dp + 1], ah, v2, v3);
    }
}

template<bool INTERIOR>
__device__ __forceinline__ void body(const float* __restrict__ qg,
                                     const float* __restrict__ kg,
                                     const float* __restrict__ vg,
                                     float* __restrict__ outg,
                                     char* smem, uint32_t smb, int ts, size_t gbase)
{
    const int t = threadIdx.x;
    const int l = t & 31;
    const int w = t >> 5;          // 0..23
    const int grp = w / 3;         // row group (16 rows), 0..7
    const int wp = w % 3;          // band third: k16 tiles [3*wp, 3*wp+3)
    const int m0 = grp * 16;
    const int qrow = l >> 2;
    const int jc = (l & 3) * 2;

    // ---- Batched fill loads: K then V then Q issued before any convert ----
    float4 kf[6], vf[6];
    #pragma unroll
    for (int i = 0; i < 6; ++i) {
        const int idx = t + i * THREADS;
        const int row = idx >> 4, c4 = idx & 15;
        const int g = ts - 64 + row;
        kf[i] = make_float4(0.f, 0.f, 0.f, 0.f);
        if ((i < 5 || idx < NCH) && (INTERIOR || (unsigned)g < (unsigned)Sc))
            kf[i] = *((const float4*)(kg + gbase + (size_t)g * Dc) + c4);
    }
    #pragma unroll
    for (int i = 0; i < 6; ++i) {
        const int idx = t + i * THREADS;
        const int row = idx >> 4, c4 = idx & 15;
        const int g = ts - 64 + row;
        vf[i] = make_float4(0.f, 0.f, 0.f, 0.f);
        if ((i < 5 || idx < NCH) && (INTERIOR || (unsigned)g < (unsigned)Sc))
            vf[i] = *((const float4*)(vg + gbase + (size_t)g * Dc) + c4);
    }
    float2 qf[4][4];
    {
        const float* qb = qg + gbase + (size_t)(ts + m0 + qrow) * Dc + jc;
        #pragma unroll
        for (int dt = 0; dt < 4; ++dt) {
            qf[dt][0] = *(const float2*)(qb + dt * 16);
            qf[dt][1] = *(const float2*)(qb + 8 * Dc + dt * 16);
            qf[dt][2] = *(const float2*)(qb + dt * 16 + 8);
            qf[dt][3] = *(const float2*)(qb + 8 * Dc + dt * 16 + 8);
        }
    }

    // ---- Convert + store K, V ----
    #pragma unroll
    for (int i = 0; i < 6; ++i) {
        const int idx = t + i * THREADS;
        if (i < 5 || idx < NCH) {
            conv_store(smem, SM_KH, idx >> 4, idx & 15, kf[i]);
            conv_store(smem, SM_VH, idx >> 4, idx & 15, vf[i]);
        }
    }
    // ---- Q fragments, fp16 pack with 2^-3*log2e folded in ----
    uint32_t qh[4][4];
    #pragma unroll
    for (int dt = 0; dt < 4; ++dt)
        #pragma unroll
        for (int j = 0; j < 4; ++j)
            qh[dt][j] = pack_h2(qf[dt][j].x * SCALE2, qf[dt][j].y * SCALE2);
    __syncthreads();

    // ---- Fused mainloop: 3 k16 tiles per warp ----
    float oacc[8][4];
    #pragma unroll
    for (int i = 0; i < 8; ++i)
        #pragma unroll
        for (int c = 0; c < 4; ++c) oacc[i][c] = 0.f;
    float dA = 0.f, dB = 0.f, dC = 0.f, dD = 0.f;

    const int krow = (l & 7) + ((l >> 4) << 3);
    const int kcol = ((l >> 3) & 1) << 3;
    const int vrow = l & 15;
    const int vcol = (l >> 4) << 3;

    if (INTERIOR) {
        if (wp == 0) {
            tile_step<1, 1>(0, smb, m0, krow, kcol, vrow, vcol, ts, qrow, jc, qh, oacc, dA, dB, dC, dD);
            tile_step<0, 0>(1, smb, m0, krow, kcol, vrow, vcol, ts, qrow, jc, qh, oacc, dA, dB, dC, dD);
            tile_step<0, 0>(2, smb, m0, krow, kcol, vrow, vcol, ts, qrow, jc, qh, oacc, dA, dB, dC, dD);
        } else if (wp == 1) {
            tile_step<0, 0>(3, smb, m0, krow, kcol, vrow, vcol, ts, qrow, jc, qh, oacc, dA, dB, dC, dD);
            tile_step<0, 0>(4, smb, m0, krow, kcol, vrow, vcol, ts, qrow, jc, qh, oacc, dA, dB, dC, dD);
            tile_step<0, 0>(5, smb, m0, krow, kcol, vrow, vcol, ts, qrow, jc, qh, oacc, dA, dB, dC, dD);
        } else {
            tile_step<0, 0>(6, smb, m0, krow, kcol, vrow, vcol, ts, qrow, jc, qh, oacc, dA, dB, dC, dD);
            tile_step<0, 0>(7, smb, m0, krow, kcol, vrow, vcol, ts, qrow, jc, qh, oacc, dA, dB, dC, dD);
            tile_step<2, 2>(8, smb, m0, krow, kcol, vrow, vcol, ts, qrow, jc, qh, oacc, dA, dB, dC, dD);
        }
    } else {
        const int TB = wp * 3;
        tile_step<3, 3>(TB,     smb, m0, krow, kcol, vrow, vcol, ts, qrow, jc, qh, oacc, dA, dB, dC, dD);
        tile_step<3, 3>(TB + 1, smb, m0, krow, kcol, vrow, vcol, ts, qrow, jc, qh, oacc, dA, dB, dC, dD);
        tile_step<3, 3>(TB + 2, smb, m0, krow, kcol, vrow, vcol, ts, qrow, jc, qh, oacc, dA, dB, dC, dD);
    }

    float den0 = dA + dB;
    float den1 = dC + dD;
    den0 += __shfl_xor_sync(0xffffffffu, den0, 1);
    den0 += __shfl_xor_sync(0xffffffffu, den0, 2);
    den1 += __shfl_xor_sync(0xffffffffu, den1, 1);
    den1 += __shfl_xor_sync(0xffffffffu, den1, 2);

    // ---- 3-way combine: warps 1,2 of each group write partials; warp 0 sums ----
    __syncthreads();   // all K/V smem reads done; whole buffer becomes scratch
    const uint32_t sb = (uint32_t)grp * 8704u;        // 8*8704 = 69632 < 73728
    if (wp != 0) {
        const uint32_t off = sb + (uint32_t)(wp - 1) * 4352u;
        #pragma unroll
        for (int dt = 0; dt < 8; ++dt)
            *(float4*)(smem + off + (uint32_t)(dt * 32 + l) * 16u) =
                make_float4(oacc[dt][0], oacc[dt][1], oacc[dt][2], oacc[dt][3]);
        if ((l & 3) == 0) {
            *(float*)(smem + off + 4096 + qrow * 8)     = den0;
            *(float*)(smem + off + 4096 + qrow * 8 + 4) = den1;
        }
    }
    __syncthreads();
    if (wp == 0) {
        #pragma unroll
        for (int part = 0; part < 2; ++part) {
            const uint32_t off = sb + (uint32_t)part * 4352u;
            #pragma unroll
            for (int dt = 0; dt < 8; ++dt) {
                const float4 p = *(const float4*)(smem + off + (uint32_t)(dt * 32 + l) * 16u);
                oacc[dt][0] += p.x; oacc[dt][1] += p.y;
                oacc[dt][2] += p.z; oacc[dt][3] += p.w;
            }
            den0 += *(const float*)(smem + off + 4096 + qrow * 8);
            den1 += *(const float*)(smem + off + 4096 + qrow * 8 + 4);
        }
        const float inv0 = 1.f / den0;
        const float inv1 = 1.f / den1;
        float* row0 = outg + gbase + (size_t)(ts + m0 + qrow) * Dc;
        float* row1 = row0 + 8 * Dc;
        #pragma unroll
        for (int dt = 0; dt < 8; ++dt) {
            const int col = dt * 8 + jc;
            *(float2*)(row0 + col) = make_float2(oacc[dt][0] * inv0, oacc[dt][1] * inv0);
            *(float2*)(row1 + col) = make_float2(oacc[dt][2] * inv1, oacc[dt][3] * inv1);
        }
    }
}

__global__ __launch_bounds__(THREADS, 1)
void swa_mma_kernel(const float* __restrict__ qg, const float* __restrict__ kg,
                    const float* __restrict__ vg, float* __restrict__ outg)
{
    extern __shared__ char smem[];
    const uint32_t smb = smem_u32(smem);
    const int ts = blockIdx.x * TQ;
    const size_t gbase = (size_t)blockIdx.y * Sc * Dc;

    if (ts >= 64 && ts + TQ + 64 <= Sc)
        body<true>(qg, kg, vg, outg, smem, smb, ts, gbase);
    else
        body<false>(qg, kg, vg, outg, smem, smb, ts, gbase);
}

extern "C" void kernel_launch(void* const* d_in, const int* in_sizes, int n_in,
                              void* d_out, int out_size)
{
    const float* q = (const float*)d_in[0];
    const float* k = (const float*)d_in[1];
    const float* v = (const float*)d_in[2];
    float* out = (float*)d_out;

    cudaFuncSetAttribute(swa_mma_kernel, cudaFuncAttributeMaxDynamicSharedMemorySize, SM_TOTAL);
    dim3 grid(Sc / TQ, 2);   // 64 x 2 = 128 CTAs, 24 warps each
    swa_mma_kernel<<<grid, THREADS, SM_TOTAL>>>(q, k, v, out);
}

// round 17
// speedup vs baseline: 1.0581x; 1.0581x over previous
#include <cuda_runtime.h>
#include <cuda_bf16.h>
#include <cstdint>

// Sliding-window attention via mma.sync fp16 (fp32 accumulate).
// B=2, S=8192, D=64, window +/-64.
// R17 = R15 math/structure re-tiled: CTA = 64 queries (8 warps: 4 row-groups
// x 2 band-half warps), grid 256, 2 CTAs co-resident per SM -> all 148 SMs
// busy and co-resident CTAs overlap each other's phases.
constexpr int Sc = 8192;
constexpr int Dc = 64;
constexpr int TQ = 64;
constexpr int NKC = 192;
constexpr int THREADS = 256;
constexpr float SCALE2 = 0.18033688f;  // 2^-3 * log2(e); exp done as ex2
constexpr int PITCH = 144;     // 144 mod 128 = 16 -> ldmatrix conflict-free

constexpr int SM_KH = 0;                      // fp16 K, 192 rows
constexpr int SM_VH = NKC * PITCH;            // 27648, fp16 V
constexpr int SM_TOTAL = 2 * NKC * PITCH;     // 55296 -> 2 CTAs/SM

#define LDSM_X4(r0, r1, r2, r3, addr) \
    asm volatile("ldmatrix.sync.aligned.m8n8.x4.shared.b16 {%0,%1,%2,%3}, [%4];" \
                 : "=r"(r0), "=r"(r1), "=r"(r2), "=r"(r3) : "r"(addr))

#define LDSM_X4_T(r0, r1, r2, r3, addr) \
    asm volatile("ldmatrix.sync.aligned.m8n8.x4.trans.shared.b16 {%0,%1,%2,%3}, [%4];" \
                 : "=r"(r0), "=r"(r1), "=r"(r2), "=r"(r3) : "r"(addr))

#define MMA_F16(c, a, b0, b1) \
    asm volatile("mma.sync.aligned.m16n8k16.row.col.f32.f16.f16.f32 " \
                 "{%0,%1,%2,%3},{%4,%5,%6,%7},{%8,%9},{%0,%1,%2,%3};" \
                 : "+f"((c)[0]), "+f"((c)[1]), "+f"((c)[2]), "+f"((c)[3]) \
                 : "r"((a)[0]), "r"((a)[1]), "r"((a)[2]), "r"((a)[3]), "r"(b0), "r"(b1))

__device__ __forceinline__ uint32_t smem_u32(const void* p) {
    uint32_t a;
    asm("{ .reg .u64 t; cvta.to.shared.u64 t, %1; cvt.u32.u64 %0, t; }" : "=r"(a) : "l"(p));
    return a;
}

__device__ __forceinline__ float ex2(float x) {
    float r;
    asm("ex2.approx.f32 %0, %1;" : "=f"(r) : "f"(x));
    return r;
}

// fp16x2 pack, a in low half.
__device__ __forceinline__ uint32_t pack_h2(float a, float b) {
    uint32_t r;
    asm("cvt.rn.f16x2.f32 %0, %1, %2;" : "=r"(r) : "f"(b), "f"(a));
    return r;
}

__device__ __forceinline__ void conv_store(char* smem, int dst, int row, int c4, float4 f) {
    const int off = row * PITCH + c4 * 8;
    *(uint2*)(smem + dst + off) = make_uint2(pack_h2(f.x, f.y), pack_h2(f.z, f.w));
}

// QK over this half's n8-tile pairs; dt OUTER so accumulator chains interleave.
template<int NTPB, int NTPC>
__device__ __forceinline__ void qk_half(uint32_t smb, int m0, int krow, int kcol,
                                        const uint32_t (&qh)[4][4],
                                        float (&sacc)[10][4])
{
    #pragma unroll
    for (int dt = 0; dt < 4; ++dt) {
        #pragma unroll
        for (int i = 0; i < NTPC; ++i) {
            const int rowb = (m0 + (NTPB + i) * 16 + krow) * PITCH;
            const int colb = (dt * 16 + kcol) * 2;
            uint32_t kh0, kh1, kh2, kh3;
            LDSM_X4(kh0, kh1, kh2, kh3, smb + SM_KH + rowb + colb);
            MMA_F16(sacc[2 * i],     qh[dt], kh0, kh1);
            MMA_F16(sacc[2 * i + 1], qh[dt], kh2, kh3);
        }
    }
}

// exp + mask + denominator + fp16 pack for one n8 tile.
// MODE 0: interior (no predicates); 1: lower band edge; 2: upper band edge;
// 3: border CTA (full checks).
template<int MODE>
__device__ __forceinline__ void exp_t(int T, int ts, int m0, int qrow, int jc,
                                      const float (&s)[4], uint32_t (&ph2)[2],
                                      float& dA, float& dB, float& dC, float& dD)
{
    const int jr = T * 8 + jc;
    float p0, p1, p2, p3;
    if (MODE == 0) {
        p0 = ex2(s[0]); p1 = ex2(s[1]); p2 = ex2(s[2]); p3 = ex2(s[3]);
    } else {
        bool v0, v1, v2, v3;
        if (MODE == 1) {
            v0 = jr >= qrow;      v1 = jr + 1 >= qrow;
            v2 = jr >= qrow + 8;  v3 = jr + 1 >= qrow + 8;
        } else if (MODE == 2) {
            v0 = jr <= qrow + 128; v1 = jr + 1 <= qrow + 128;
            v2 = jr <= qrow + 136; v3 = jr + 1 <= qrow + 136;
        } else {
            const int g0 = ts - 64 + m0 + jr;
            const bool b0 = (unsigned)g0 < (unsigned)Sc;
            const bool b1 = (unsigned)(g0 + 1) < (unsigned)Sc;
            v0 = (jr >= qrow) && (jr <= qrow + 128) && b0;
            v1 = (jr + 1 >= qrow) && (jr + 1 <= qrow + 128) && b1;
            v2 = (jr >= qrow + 8) && (jr <= qrow + 136) && b0;
            v3 = (jr + 1 >= qrow + 8) && (jr + 1 <= qrow + 136) && b1;
        }
        p0 = v0 ? ex2(s[0]) : 0.f;
        p1 = v1 ? ex2(s[1]) : 0.f;
        p2 = v2 ? ex2(s[2]) : 0.f;
        p3 = v3 ? ex2(s[3]) : 0.f;
    }
    dA += p0; dB += p1; dC += p2; dD += p3;
    ph2[0] = pack_h2(p0, p1);   // rows qrow   : A-frag low pair
    ph2[1] = pack_h2(p2, p3);   // rows qrow+8
}

// PV single-term fp16: P fragments already packed (ph), V from fp16 buffer.
template<int KTB, int KTC>
__device__ __forceinline__ void pv_half(uint32_t smb, int m0, int vrow, int vcol,
                                        const uint32_t (&ph)[10][2],
                                        float (&oacc)[8][4])
{
    #pragma unroll
    for (int k = 0; k < KTC; ++k) {
        const uint32_t ah[4] = { ph[2 * k][0], ph[2 * k][1],
                                 ph[2 * k + 1][0], ph[2 * k + 1][1] };
        const int rowb = (m0 + (KTB + k) * 16 + vrow) * PITCH;
        #pragma unroll
        for (int dp = 0; dp < 4; ++dp) {
            const int colb = (dp * 16 + vcol) * 2;
            uint32_t vh0, vh1, vh2, vh3;
            LDSM_X4_T(vh0, vh1, vh2, vh3, smb + SM_VH + rowb + colb);
            MMA_F16(oacc[2 * dp],     ah, vh0, vh1);
            MMA_F16(oacc[2 * dp + 1], ah, vh2, vh3);
        }
    }
}

template<bool INTERIOR>
__device__ __forceinline__ void body(const float* __restrict__ qg,
                                     const float* __restrict__ kg,
                                     const float* __restrict__ vg,
                                     float* __restrict__ outg,
                                     char* smem, uint32_t smb, int ts, size_t gbase)
{
    const int t = threadIdx.x;
    const int l = t & 31;
    const int grp = t >> 6;        // row group (16 rows each), 0..3
    const int half = (t >> 5) & 1; // band half: 0 -> tiles 0-9, 1 -> tiles 10-17
    const int m0 = grp * 16;
    const int qrow = l >> 2;
    const int jc = (l & 3) * 2;

    // ---- Batched K fill loads (12 LDG.128 in flight) ----
    float4 kf[12];
    #pragma unroll
    for (int i = 0; i < 12; ++i) {
        const int idx = t + i * THREADS;
        const int row = idx >> 4, c4 = idx & 15;
        const int g = ts - 64 + row;
        if (INTERIOR || (unsigned)g < (unsigned)Sc)
            kf[i] = *((const float4*)(kg + gbase + (size_t)g * Dc) + c4);
        else
            kf[i] = make_float4(0.f, 0.f, 0.f, 0.f);
    }
    // ---- Q loads (land while K converts) ----
    float2 qf[4][4];
    {
        const float* qb = qg + gbase + (size_t)(ts + m0 + qrow) * Dc + jc;
        #pragma unroll
        for (int dt = 0; dt < 4; ++dt) {
            qf[dt][0] = *(const float2*)(qb + dt * 16);
            qf[dt][1] = *(const float2*)(qb + 8 * Dc + dt * 16);
            qf[dt][2] = *(const float2*)(qb + dt * 16 + 8);
            qf[dt][3] = *(const float2*)(qb + 8 * Dc + dt * 16 + 8);
        }
    }
    // ---- Convert + store K ----
    #pragma unroll
    for (int i = 0; i < 12; ++i) {
        const int idx = t + i * THREADS;
        conv_store(smem, SM_KH, idx >> 4, idx & 15, kf[i]);
    }
    // ---- Batched V fill loads, then convert ----
    float4 vf[12];
    #pragma unroll
    for (int i = 0; i < 12; ++i) {
        const int idx = t + i * THREADS;
        const int row = idx >> 4, c4 = idx & 15;
        const int g = ts - 64 + row;
        if (INTERIOR || (unsigned)g < (unsigned)Sc)
            vf[i] = *((const float4*)(vg + gbase + (size_t)g * Dc) + c4);
        else
            vf[i] = make_float4(0.f, 0.f, 0.f, 0.f);
    }
    // ---- Q fragments, fp16 pack with 2^-3*log2e folded in ----
    uint32_t qh[4][4];
    #pragma unroll
    for (int dt = 0; dt < 4; ++dt)
        #pragma unroll
        for (int j = 0; j < 4; ++j)
            qh[dt][j] = pack_h2(qf[dt][j].x * SCALE2, qf[dt][j].y * SCALE2);
    #pragma unroll
    for (int i = 0; i < 12; ++i) {
        const int idx = t + i * THREADS;
        conv_store(smem, SM_VH, idx >> 4, idx & 15, vf[i]);
    }
    __syncthreads();

    // ---- QK on this warp's band half ----
    float sacc[10][4];
    #pragma unroll
    for (int i = 0; i < 10; ++i)
        #pragma unroll
        for (int c = 0; c < 4; ++c) sacc[i][c] = 0.f;

    const int krow = (l & 7) + ((l >> 4) << 3);
    const int kcol = ((l >> 3) & 1) << 3;
    if (half == 0) qk_half<0, 5>(smb, m0, krow, kcol, qh, sacc);
    else           qk_half<5, 4>(smb, m0, krow, kcol, qh, sacc);

    // ---- exp + mask (edge tiles only) + pack to fp16 fragments ----
    uint32_t ph[10][2];
    float dA = 0.f, dB = 0.f, dC = 0.f, dD = 0.f;
    if (INTERIOR) {
        if (half == 0) {
            exp_t<1>(0, ts, m0, qrow, jc, sacc[0], ph[0], dA, dB, dC, dD);
            exp_t<1>(1, ts, m0, qrow, jc, sacc[1], ph[1], dA, dB, dC, dD);
            #pragma unroll
            for (int i = 2; i < 10; ++i)
                exp_t<0>(i, ts, m0, qrow, jc, sacc[i], ph[i], dA, dB, dC, dD);
        } else {
            #pragma unroll
            for (int i = 0; i < 6; ++i)
                exp_t<0>(10 + i, ts, m0, qrow, jc, sacc[i], ph[i], dA, dB, dC, dD);
            exp_t<2>(16, ts, m0, qrow, jc, sacc[6], ph[6], dA, dB, dC, dD);
            exp_t<2>(17, ts, m0, qrow, jc, sacc[7], ph[7], dA, dB, dC, dD);
        }
    } else {
        if (half == 0) {
            #pragma unroll
            for (int i = 0; i < 10; ++i)
                exp_t<3>(i, ts, m0, qrow, jc, sacc[i], ph[i], dA, dB, dC, dD);
        } else {
            #pragma unroll
            for (int i = 0; i < 8; ++i)
                exp_t<3>(10 + i, ts, m0, qrow, jc, sacc[i], ph[i], dA, dB, dC, dD);
        }
    }
    float den0 = dA + dB;
    float den1 = dC + dD;
    den0 += __shfl_xor_sync(0xffffffffu, den0, 1);
    den0 += __shfl_xor_sync(0xffffffffu, den0, 2);
    den1 += __shfl_xor_sync(0xffffffffu, den1, 1);
    den1 += __shfl_xor_sync(0xffffffffu, den1, 2);

    // ---- PV on this warp's band half (single-term fp16) ----
    float oacc[8][4];
    #pragma unroll
    for (int i = 0; i < 8; ++i)
        #pragma unroll
        for (int c = 0; c < 4; ++c) oacc[i][c] = 0.f;

    const int vrow = l & 15;
    const int vcol = (l >> 4) << 3;
    if (half == 0) pv_half<0, 5>(smb, m0, vrow, vcol, ph, oacc);
    else           pv_half<5, 4>(smb, m0, vrow, vcol, ph, oacc);

    // ---- Combine warp-pair partials via smem (K region becomes scratch) ----
    __syncthreads();   // all QK/PV smem reads done
    const uint32_t pairbase = (uint32_t)grp * 4352u;   // 4 * 4352 = 17408 < 27648
    if (half == 1) {
        #pragma unroll
        for (int dt = 0; dt < 8; ++dt)
            *(float4*)(smem + pairbase + (uint32_t)(dt * 32 + l) * 16u) =
                make_float4(oacc[dt][0], oacc[dt][1], oacc[dt][2], oacc[dt][3]);
        if ((l & 3) == 0) {
            *(float*)(smem + pairbase + 4096 + qrow * 8)     = den0;
            *(float*)(smem + pairbase + 4096 + qrow * 8 + 4) = den1;
        }
    }
    __syncthreads();
    if (half == 0) {
        #pragma unroll
        for (int dt = 0; dt < 8; ++dt) {
            const float4 p = *(const float4*)(smem + pairbase + (uint32_t)(dt * 32 + l) * 16u);
            oacc[dt][0] += p.x; oacc[dt][1] += p.y;
            oacc[dt][2] += p.z; oacc[dt][3] += p.w;
        }
        den0 += *(const float*)(smem + pairbase + 4096 + qrow * 8);
        den1 += *(const float*)(smem + pairbase + 4096 + qrow * 8 + 4);

        const float inv0 = 1.f / den0;
        const float inv1 = 1.f / den1;
        float* row0 = outg + gbase + (size_t)(ts + m0 + qrow) * Dc;
        float* row1 = row0 + 8 * Dc;
        #pragma unroll
        for (int dt = 0; dt < 8; ++dt) {
            const int col = dt * 8 + jc;
            *(float2*)(row0 + col) = make_float2(oacc[dt][0] * inv0, oacc[dt][1] * inv0);
            *(float2*)(row1 + col) = make_float2(oacc[dt][2] * inv1, oacc[dt][3] * inv1);
        }
    }
}

__global__ __launch_bounds__(THREADS, 2)
void swa_mma_kernel(const float* __restrict__ qg, const float* __restrict__ kg,
                    const float* __restrict__ vg, float* __restrict__ outg)
{
    extern __shared__ char smem[];
    const uint32_t smb = smem_u32(smem);
    const int ts = blockIdx.x * TQ;
    const size_t gbase = (size_t)blockIdx.y * Sc * Dc;

    if (ts >= 64 && ts + TQ + 64 <= Sc)
        body<true>(qg, kg, vg, outg, smem, smb, ts, gbase);
    else
        body<false>(qg, kg, vg, outg, smem, smb, ts, gbase);
}

extern "C" void kernel_launch(void* const* d_in, const int* in_sizes, int n_in,
                              void* d_out, int out_size)
{
    const float* q = (const float*)d_in[0];
    const float* k = (const float*)d_in[1];
    const float* v = (const float*)d_in[2];
    float* out = (float*)d_out;

    cudaFuncSetAttribute(swa_mma_kernel, cudaFuncAttributeMaxDynamicSharedMemorySize, SM_TOTAL);
    dim3 grid(Sc / TQ, 2);   // 128 x 2 = 256 CTAs, 2 co-resident per SM
    swa_mma_kernel<<<grid, THREADS, SM_TOTAL>>>(q, k, v, out);
}